// round 1
// baseline (speedup 1.0000x reference)
#include <cuda_runtime.h>
#include <cstdint>

#define DD 128
#define KK 32
#define NTHREADS 256
#define NBLOCKS 444

// shared memory layout (floats), all tables transposed [knot][dim] so that
// bank = dim mod 32 = lane  -> conflict-free LDS for any bin index
#define XPOS_OFF 0
#define YPOS_OFF (33 * DD)
#define SLOPE_OFF (2 * 33 * DD)
#define INVBW_OFF (3 * 33 * DD)
#define SMEM_FLOATS (3 * 33 * DD + 32 * DD)

__global__ void __launch_bounds__(NTHREADS)
rqs_kernel(const float* __restrict__ x,
           const float* __restrict__ sp,
           float* __restrict__ y_out,
           float* __restrict__ ld_out,
           int n_rows)
{
    extern __shared__ float sm[];
    float* s_xpos  = sm + XPOS_OFF;   // (K+1) x D
    float* s_ypos  = sm + YPOS_OFF;   // (K+1) x D
    float* s_slope = sm + SLOPE_OFF;  // (K+1) x D
    float* s_invbw = sm + INVBW_OFF;  // K x D

    const int tid = threadIdx.x;
    const float TOTAL_M = 10.0f - KK * 1e-4f;  // (range) - K*min_bin_size

    // ---- per-block table build (redundant across blocks, trivially cheap) ----
    if (tid < DD) {
        // widths -> x_pos, inv bin width
        const int d = tid;
        const float* uw = sp + d * (3 * KK + 1);
        float m = -1e30f;
        #pragma unroll 1
        for (int k = 0; k < KK; k++) m = fmaxf(m, uw[k]);
        float s = 0.f;
        #pragma unroll 1
        for (int k = 0; k < KK; k++) s += __expf(uw[k] - m);
        float scale = TOTAL_M / s;
        float run = -5.0f;
        s_xpos[d] = run;
        #pragma unroll 1
        for (int k = 0; k < KK; k++) {
            float w = __expf(uw[k] - m) * scale + 1e-4f;
            float nxt = run + w;
            s_xpos[(k + 1) * DD + d] = nxt;
            s_invbw[k * DD + d] = 1.0f / (nxt - run);  // exact fl-diff like reference
            run = nxt;
        }
    } else {
        // heights -> y_pos, and slopes
        const int d = tid - DD;
        const float* uh = sp + d * (3 * KK + 1) + KK;
        const float* us = sp + d * (3 * KK + 1) + 2 * KK;
        float m = -1e30f;
        #pragma unroll 1
        for (int k = 0; k < KK; k++) m = fmaxf(m, uh[k]);
        float s = 0.f;
        #pragma unroll 1
        for (int k = 0; k < KK; k++) s += __expf(uh[k] - m);
        float scale = TOTAL_M / s;
        float run = -5.0f;
        s_ypos[d] = run;
        #pragma unroll 1
        for (int k = 0; k < KK; k++) {
            float h = __expf(uh[k] - m) * scale + 1e-4f;
            run += h;
            s_ypos[(k + 1) * DD + d] = run;
        }
        // slopes = softplus(us + offset) + min_knot_slope
        const float OFFS = 0.5411666430f;  // log(expm1(1 - 1e-4)) in fp64, rounded
        #pragma unroll 1
        for (int k = 0; k <= KK; k++) {
            float v = us[k] + OFFS;
            float spv = fmaxf(v, 0.f) + __logf(1.f + __expf(-fabsf(v)));
            s_slope[k * DD + d] = spv + 1e-4f;
        }
    }
    __syncthreads();

    // ---- main loop: one warp per row, lane handles dims lane+32j, j=0..3 ----
    const int lane = tid & 31;
    const int warp = (blockIdx.x * NTHREADS + tid) >> 5;
    const int nwarps = gridDim.x * (NTHREADS >> 5);
    const float LN2 = 0.69314718055994531f;

    for (int row = warp; row < n_rows; row += nwarps) {
        const float* xr = x + (size_t)row * DD;
        float prod = 1.0f;
        float yv[4];

        #pragma unroll
        for (int j = 0; j < 4; j++) {
            const int d = lane + 32 * j;
            float xv = xr[d];

            // binary search: largest idx in [0,31] with xpos[idx] <= x (side='right')
            int idx = 0;
            #pragma unroll
            for (int step = 16; step; step >>= 1) {
                float kv = s_xpos[(idx + step) * DD + d];
                if (xv >= kv) idx += step;
            }
            const int o = idx * DD + d;

            float x0 = s_xpos[o];
            float y0 = s_ypos[o];
            float y1 = s_ypos[o + DD];
            float s0 = s_slope[o];
            float s1 = s_slope[o + DD];
            float ib = s_invbw[o];

            float zr   = (xv - x0) * ib;
            float z    = fminf(fmaxf(zr, 0.f), 1.f);
            float bh   = y1 - y0;
            float bs   = bh * ib;
            float sqz  = z * z;
            float z1mz = z - sqz;
            float omz  = 1.f - z;
            float sq1  = omz * omz;

            float st  = (s0 + s1) - 2.f * bs;
            float den = fmaf(st, z1mz, bs);
            float num = bh * fmaf(s0, z1mz, bs * sqz);

            float r;
            asm("rcp.approx.f32 %0, %1;" : "=f"(r) : "f"(den));
            float yy = fmaf(num, r, y0);

            // derivative = bs^2 * arg / den^2 ; fold bs^2 via t = bs * (1/den)
            float arg = fmaf(s1, sqz, fmaf(s0, sq1, (bs + bs) * z1mz));
            float t   = bs * r;
            float deriv = (t * t) * arg;

            // out-of-range tails (P ~ 6e-7): linear extrapolation with edge slopes
            if (zr != z) {
                if (zr < 0.f) {
                    yy = fmaf(xv - x0, s0, y0);
                    deriv = s0;
                } else {
                    float x1 = s_xpos[o + DD];
                    yy = fmaf(xv - x1, s1, y1);
                    deriv = s1;
                }
            }
            prod *= deriv;
            yv[j] = yy;
        }

        float* yr = y_out + (size_t)row * DD;
        #pragma unroll
        for (int j = 0; j < 4; j++) yr[lane + 32 * j] = yv[j];

        // one LG2 per 4 elements, then warp-sum; scale by ln2 once per row
        float ls = __log2f(prod);
        #pragma unroll
        for (int off = 16; off; off >>= 1)
            ls += __shfl_xor_sync(0xffffffffu, ls, off);
        if (lane == 0) ld_out[row] = ls * LN2;
    }
}

extern "C" void kernel_launch(void* const* d_in, const int* in_sizes, int n_in,
                              void* d_out, int out_size)
{
    const float* x  = (const float*)d_in[0];
    const float* sp = (const float*)d_in[1];
    const int n_rows = in_sizes[0] / DD;

    float* y_out  = (float*)d_out;
    float* ld_out = (float*)d_out + (size_t)n_rows * DD;

    const size_t smem = SMEM_FLOATS * sizeof(float);
    cudaFuncSetAttribute(rqs_kernel, cudaFuncAttributeMaxDynamicSharedMemorySize,
                         (int)smem);
    rqs_kernel<<<NBLOCKS, NTHREADS, smem>>>(x, sp, y_out, ld_out, n_rows);
}

// round 2
// speedup vs baseline: 1.0683x; 1.0683x over previous
#include <cuda_runtime.h>
#include <cstdint>

#define DD 128
#define KK 32
#define NTHREADS 512
#define NBLOCKS 444

// shared memory layout (floats), all tables transposed [knot][dim] so that
// bank = dim mod 32 = lane  -> conflict-free LDS for any bin index
#define XPOS_OFF 0
#define YPOS_OFF (33 * DD)
#define SLOPE_OFF (2 * 33 * DD)
#define INVBW_OFF (3 * 33 * DD)
#define SMEM_FLOATS (3 * 33 * DD + 32 * DD)

__global__ void __launch_bounds__(NTHREADS, 3)
rqs_kernel(const float* __restrict__ x,
           const float* __restrict__ sp,
           float* __restrict__ y_out,
           float* __restrict__ ld_out,
           int n_rows)
{
    extern __shared__ float sm[];
    float* s_xpos  = sm + XPOS_OFF;   // (K+1) x D
    float* s_ypos  = sm + YPOS_OFF;   // (K+1) x D
    float* s_slope = sm + SLOPE_OFF;  // (K+1) x D
    float* s_invbw = sm + INVBW_OFF;  // K x D

    const int tid = threadIdx.x;
    const float TOTAL_M = 10.0f - KK * 1e-4f;  // (range) - K*min_bin_size

    // ---- per-block table build (redundant across blocks, trivially cheap) ----
    if (tid < DD) {
        // widths -> x_pos, inv bin width
        const int d = tid;
        const float* uw = sp + d * (3 * KK + 1);
        float m = -1e30f;
        #pragma unroll 1
        for (int k = 0; k < KK; k++) m = fmaxf(m, uw[k]);
        float s = 0.f;
        #pragma unroll 1
        for (int k = 0; k < KK; k++) s += __expf(uw[k] - m);
        float scale = TOTAL_M / s;
        float run = -5.0f;
        s_xpos[d] = run;
        #pragma unroll 1
        for (int k = 0; k < KK; k++) {
            float w = __expf(uw[k] - m) * scale + 1e-4f;
            float nxt = run + w;
            s_xpos[(k + 1) * DD + d] = nxt;
            s_invbw[k * DD + d] = 1.0f / (nxt - run);
            run = nxt;
        }
    } else if (tid < 2 * DD) {
        // heights -> y_pos, and slopes
        const int d = tid - DD;
        const float* uh = sp + d * (3 * KK + 1) + KK;
        const float* us = sp + d * (3 * KK + 1) + 2 * KK;
        float m = -1e30f;
        #pragma unroll 1
        for (int k = 0; k < KK; k++) m = fmaxf(m, uh[k]);
        float s = 0.f;
        #pragma unroll 1
        for (int k = 0; k < KK; k++) s += __expf(uh[k] - m);
        float scale = TOTAL_M / s;
        float run = -5.0f;
        s_ypos[d] = run;
        #pragma unroll 1
        for (int k = 0; k < KK; k++) {
            float h = __expf(uh[k] - m) * scale + 1e-4f;
            run += h;
            s_ypos[(k + 1) * DD + d] = run;
        }
        // slopes = softplus(us + offset) + min_knot_slope
        const float OFFS = 0.5411666430f;  // log(expm1(1 - 1e-4))
        #pragma unroll 1
        for (int k = 0; k <= KK; k++) {
            float v = us[k] + OFFS;
            float spv = fmaxf(v, 0.f) + __logf(1.f + __expf(-fabsf(v)));
            s_slope[k * DD + d] = spv + 1e-4f;
        }
    }
    __syncthreads();

    // ---- main loop: one warp per row, lane handles dims lane+32j, j=0..3 ----
    const int lane = tid & 31;
    const int warp = (blockIdx.x * NTHREADS + tid) >> 5;
    const int nwarps = gridDim.x * (NTHREADS >> 5);
    const float LN2 = 0.69314718055994531f;

    for (int row = warp; row < n_rows; row += nwarps) {
        const float* xr = x + (size_t)row * DD;
        float prod = 1.0f;
        float yv[4];

        #pragma unroll
        for (int j = 0; j < 4; j++) {
            const int d = lane + 32 * j;
            float xv = xr[d];

            // binary search: largest idx in [0,31] with xpos[idx] <= x.
            // Track the accepted knot value -> x0 comes out of the search
            // for free (xpos[0] = -5 is a compile-time constant).
            int idx = 0;
            float x0 = -5.0f;
            #pragma unroll
            for (int step = 16; step; step >>= 1) {
                float kv = s_xpos[(idx + step) * DD + d];
                if (xv >= kv) { idx += step; x0 = kv; }
            }
            const int o = idx * DD + d;

            float y0 = s_ypos[o];
            float y1 = s_ypos[o + DD];
            float s0 = s_slope[o];
            float s1 = s_slope[o + DD];
            float ib = s_invbw[o];

            float zr   = (xv - x0) * ib;
            float z    = fminf(fmaxf(zr, 0.f), 1.f);
            float bh   = y1 - y0;
            float bs   = bh * ib;
            float sqz  = z * z;
            float z1mz = z - sqz;
            float omz  = 1.f - z;
            float sq1  = omz * omz;

            float st  = (s0 + s1) - 2.f * bs;
            float den = fmaf(st, z1mz, bs);
            float num = bh * fmaf(s0, z1mz, bs * sqz);

            float r;
            asm("rcp.approx.f32 %0, %1;" : "=f"(r) : "f"(den));
            float yy = fmaf(num, r, y0);

            // derivative = bs^2 * arg / den^2 ; fold bs^2 via t = bs * (1/den)
            float arg = fmaf(s1, sqz, fmaf(s0, sq1, (bs + bs) * z1mz));
            float t   = bs * r;
            float deriv = (t * t) * arg;

            // out-of-range tails (P ~ 6e-7): linear extrapolation, edge slopes
            if (zr != z) {
                if (zr < 0.f) {
                    yy = fmaf(xv - x0, s0, y0);
                    deriv = s0;
                } else {
                    float x1 = s_xpos[o + DD];
                    yy = fmaf(xv - x1, s1, y1);
                    deriv = s1;
                }
            }
            prod *= deriv;
            yv[j] = yy;
        }

        float* yr = y_out + (size_t)row * DD;
        #pragma unroll
        for (int j = 0; j < 4; j++) yr[lane + 32 * j] = yv[j];

        // one LG2 per 4 elements, then warp-sum; scale by ln2 once per row
        float ls = __log2f(prod);
        #pragma unroll
        for (int off = 16; off; off >>= 1)
            ls += __shfl_xor_sync(0xffffffffu, ls, off);
        if (lane == 0) ld_out[row] = ls * LN2;
    }
}

extern "C" void kernel_launch(void* const* d_in, const int* in_sizes, int n_in,
                              void* d_out, int out_size)
{
    const float* x  = (const float*)d_in[0];
    const float* sp = (const float*)d_in[1];
    const int n_rows = in_sizes[0] / DD;

    float* y_out  = (float*)d_out;
    float* ld_out = (float*)d_out + (size_t)n_rows * DD;

    const size_t smem = SMEM_FLOATS * sizeof(float);
    cudaFuncSetAttribute(rqs_kernel, cudaFuncAttributeMaxDynamicSharedMemorySize,
                         (int)smem);
    rqs_kernel<<<NBLOCKS, NTHREADS, smem>>>(x, sp, y_out, ld_out, n_rows);
}